// round 16
// baseline (speedup 1.0000x reference)
#include <cuda_runtime.h>
#include <cuda_bf16.h>
#include <math.h>
#include <stdint.h>

// Problem constants
#define KK    64
#define DD    512
#define TT    128
#define BB    512
#define BOS_T 63
#define EOS_T 62
#define LOG64 4.158883083359672f

#define BROW  1040            // B smem row stride bytes (512*2 + 16 pad)
#define SMEM_EMIT (64 * BROW) // 66560 B

// Emission probabilities exp(wb)/64 (cols 62,63 zeroed): [seq][t][k] f32 = 16 MB
__device__ float g_swb[(size_t)BB * TT * KK];

__device__ __forceinline__ uint32_t pk(float a, float b) {
    __nv_bfloat162 h = __floats2bfloat162_rn(a, b);
    return *reinterpret_cast<uint32_t*>(&h);
}
__device__ __forceinline__ uint32_t pk2(float2 v) { return pk(v.x, v.y); }

__device__ __forceinline__ void mma16816(float* c, uint32_t a0, uint32_t a1,
                                         uint32_t a2, uint32_t a3,
                                         uint32_t b0, uint32_t b1) {
    asm volatile(
        "mma.sync.aligned.m16n8k16.row.col.f32.bf16.bf16.f32 "
        "{%0,%1,%2,%3}, {%4,%5,%6,%7}, {%8,%9}, {%0,%1,%2,%3};"
        : "+f"(c[0]), "+f"(c[1]), "+f"(c[2]), "+f"(c[3])
        : "r"(a0), "r"(a1), "r"(a2), "r"(a3), "r"(b0), "r"(b1));
}

__device__ __forceinline__ void ldsm4(uint32_t& r0, uint32_t& r1,
                                      uint32_t& r2, uint32_t& r3, uint32_t addr) {
    asm volatile("ldmatrix.sync.aligned.m8n8.x4.shared.b16 {%0,%1,%2,%3}, [%4];"
                 : "=r"(r0), "=r"(r1), "=r"(r2), "=r"(r3) : "r"(addr));
}

// ---------------------------------------------------------------------------
// Kernel 1: emission, direct-LDG A fragments, ring-3 register prefetch.
// 512 CTAs = one sequence each: M=128 t-rows x N=64 tags x K=512.
// ThetaB converted to bf16 SMEM once; mainloop barrier-free.
// ---------------------------------------------------------------------------
__global__ __launch_bounds__(256, 2)
void emit_kernel(const float* __restrict__ ThetaB,
                 const float* __restrict__ E,
                 const int*   __restrict__ words)
{
    extern __shared__ char sm[];
    const int b    = blockIdx.x;
    const int tid  = threadIdx.x;
    const int wid  = tid >> 5, lane = tid & 31;
    const int g    = lane >> 2, t4 = lane & 3;
    const int m0   = wid * 16;

    // ---- stage ThetaB -> bf16 SMEM, full K (once) ----
    {
        const int row = tid >> 2, q = tid & 3;                 // 4 thr/row
        const float4* tp = (const float4*)(ThetaB + row * DD + q * 32);
        char* dst = sm + row * BROW + q * 64;
#pragma unroll
        for (int c = 0; c < 4; ++c) {
            float4 tr[8];
#pragma unroll
            for (int j = 0; j < 8; ++j) tr[j] = tp[c * 32 + j];
#pragma unroll
            for (int jj = 0; jj < 4; ++jj) {
                float4 g0 = tr[2 * jj], g1 = tr[2 * jj + 1];
                *(uint4*)(dst + c * 256 + jj * 16) =
                    make_uint4(pk(g0.x, g0.y), pk(g0.z, g0.w),
                               pk(g1.x, g1.y), pk(g1.z, g1.w));
            }
        }
    }
    __syncthreads();            // only barrier before epilogue

    // ---- A row pointers (two E rows per thread) ----
    const float* p0 = E + (size_t)words[b * TT + m0 + g] * DD;
    const float* p1 = E + (size_t)words[b * TT + m0 + 8 + g] * DD;
    const int koff = 2 * t4;

    // B ldsm base (proven lane mapping, row stride BROW)
    const uint32_t base = (uint32_t)__cvta_generic_to_shared(sm);
    const uint32_t aB = base
        + (uint32_t)(((((lane >> 4) & 1) * 8 + (lane & 7)) * BROW)
        + ((lane >> 3) & 1) * 16);

    float acc[8][4];
#pragma unroll
    for (int nt = 0; nt < 8; ++nt)
#pragma unroll
        for (int r = 0; r < 4; ++r) acc[nt][r] = 0.f;

    // ring-3 register buffer: one group = 2 k-steps = 8 float2 per thread
    float2 buf[3][8];
#define LOADG(grp, d)                                                    \
    {                                                                    \
        const int s0 = (grp) * 2;                                        \
        (d)[0] = *(const float2*)(p0 + 16 * s0 + koff);                  \
        (d)[1] = *(const float2*)(p0 + 16 * s0 + koff + 8);              \
        (d)[2] = *(const float2*)(p1 + 16 * s0 + koff);                  \
        (d)[3] = *(const float2*)(p1 + 16 * s0 + koff + 8);              \
        (d)[4] = *(const float2*)(p0 + 16 * s0 + 16 + koff);             \
        (d)[5] = *(const float2*)(p0 + 16 * s0 + 16 + koff + 8);         \
        (d)[6] = *(const float2*)(p1 + 16 * s0 + 16 + koff);             \
        (d)[7] = *(const float2*)(p1 + 16 * s0 + 16 + koff + 8);         \
    }

    LOADG(0, buf[0]);
    LOADG(1, buf[1]);
    LOADG(2, buf[2]);
#pragma unroll
    for (int grp = 0; grp < 16; ++grp) {
        const int ri = grp % 3;
        // extract this group's fragments into packed regs (frees the buffer)
        uint32_t a[8];
#pragma unroll
        for (int i = 0; i < 8; ++i) a[i] = pk2(buf[ri][i]);
        if (grp <= 12) LOADG(grp + 3, buf[ri]);   // refill during MMA
#pragma unroll
        for (int ss = 0; ss < 2; ++ss) {
            const int s = grp * 2 + ss;
            const uint32_t a0 = a[ss * 4 + 0];    // row m0+g,   k lo
            const uint32_t a2 = a[ss * 4 + 1];    // row m0+g,   k hi
            const uint32_t a1 = a[ss * 4 + 2];    // row m0+8+g, k lo
            const uint32_t a3 = a[ss * 4 + 3];    // row m0+8+g, k hi
#pragma unroll
            for (int i = 0; i < 4; ++i) {
                uint32_t b0, b1, b2, b3;
                ldsm4(b0, b1, b2, b3, aB + i * (16 * BROW) + s * 32);
                mma16816(acc[2 * i],     a0, a1, a2, a3, b0, b1);
                mma16816(acc[2 * i + 1], a0, a1, a2, a3, b2, b3);
            }
        }
    }
#undef LOADG

    // ---- epilogue: exp/64, mask cols 62/63, write f32 ----
    const float inv = 1.0f / 64.0f;
    float* obase = g_swb + (size_t)b * TT * KK;
    const int t0 = m0 + g, t1 = m0 + 8 + g;
#pragma unroll
    for (int nt = 0; nt < 8; ++nt) {
        const int col = nt * 8 + t4 * 2;
        const bool msk = (col == EOS_T);
        float2 v0, v1;
        v0.x = msk ? 0.f : __expf(acc[nt][0]) * inv;
        v0.y = msk ? 0.f : __expf(acc[nt][1]) * inv;
        v1.x = msk ? 0.f : __expf(acc[nt][2]) * inv;
        v1.y = msk ? 0.f : __expf(acc[nt][3]) * inv;
        *(float2*)(obase + t0 * KK + col) = v0;
        *(float2*)(obase + t1 * KK + col) = v1;
    }
}

// ---------------------------------------------------------------------------
// Kernel 2: one WARP per sequence, shfl-broadcast recursion (no SMEM/barrier
// in the step loop). Lane owns outputs k=lane, k=lane+32; alpha distributed
// 2 values/lane; 64 unrolled shfl broadcasts + 128 FMA per step.
// ---------------------------------------------------------------------------
__global__ __launch_bounds__(32)
void forward_kernel(const float* __restrict__ WA,
                    const int*   __restrict__ tags,
                    float*       __restrict__ out)
{
    __shared__ __align__(16) float swb_s[126 * KK];   // rows t=1..126

    const int lane = threadIdx.x;
    const int b    = blockIdx.x;

    // stage emission rows 1..126 (pure copy; exp/64+mask already applied)
    {
        const float4* src = (const float4*)(g_swb + (size_t)b * TT * KK + KK);
        float4* dst = (float4*)swb_s;
        for (int i = lane; i < 126 * 16; i += 32) dst[i] = src[i];
    }

    // A columns for k=lane and k=lane+32 in registers
    float A0[KK], A1[KK];
#pragma unroll
    for (int j = 0; j < KK; ++j) {
        A0[j] = __expf(WA[j * KK + lane]);
        A1[j] = __expf(WA[j * KK + lane + 32]);
    }
    __syncwarp();

    // tagged closed form
    float tagc = 0.f;
    for (int t = lane + 1; t <= 126; t += 32) {
        const int ct = tags[b * TT + t];
        const int pt = (t == 1) ? BOS_T : tags[b * TT + t - 1];
        tagc += __logf(swb_s[(t - 1) * KK + ct]) + LOG64 + WA[pt * KK + ct];
    }
    if (lane == 0) tagc += WA[tags[b * TT + 126] * KK + EOS_T];
#pragma unroll
    for (int o = 16; o > 0; o >>= 1) tagc += __shfl_down_sync(0xffffffffu, tagc, o);
    const float tagged = tagc;                         // valid on lane 0

    // forward recursion: alpha distributed, shfl broadcast per step
    float alo = A0[BOS_T] * swb_s[lane];               // t=1 row at offset 0
    float ahi = A1[BOS_T] * swb_s[lane + 32];

    for (int t = 2; t <= 126; ++t) {
        float c0[4] = {0.f, 0.f, 0.f, 0.f};
        float c1[4] = {0.f, 0.f, 0.f, 0.f};
#pragma unroll
        for (int j = 0; j < 32; ++j) {
            const float aj = __shfl_sync(0xffffffffu, alo, j);
            c0[j & 3] = fmaf(aj, A0[j], c0[j & 3]);
            c1[j & 3] = fmaf(aj, A1[j], c1[j & 3]);
        }
#pragma unroll
        for (int j = 0; j < 32; ++j) {
            const float aj = __shfl_sync(0xffffffffu, ahi, j);
            c0[j & 3] = fmaf(aj, A0[32 + j], c0[j & 3]);
            c1[j & 3] = fmaf(aj, A1[32 + j], c1[j & 3]);
        }
        const float* eb = swb_s + (t - 1) * KK;
        alo = ((c0[0] + c0[1]) + (c0[2] + c0[3])) * eb[lane];
        ahi = ((c1[0] + c1[1]) + (c1[2] + c1[3])) * eb[lane + 32];
    }

    float contrib = alo * __expf(WA[lane * KK + EOS_T])
                  + ahi * __expf(WA[(lane + 32) * KK + EOS_T]);
#pragma unroll
    for (int o = 16; o > 0; o >>= 1) contrib += __shfl_down_sync(0xffffffffu, contrib, o);

    if (lane == 0)
        out[b] = tagged - (__logf(contrib) + 126.0f * LOG64);
}

// ---------------------------------------------------------------------------
// Inputs: WA[64*64] f32, ThetaB[64*512] f32, E[100000*512] f32,
//         words[512*128] i32, tags[512*128] i32  ->  out f32[512]
// ---------------------------------------------------------------------------
extern "C" void kernel_launch(void* const* d_in, const int* in_sizes, int n_in,
                              void* d_out, int out_size)
{
    const float* WA     = (const float*)d_in[0];
    const float* ThetaB = (const float*)d_in[1];
    const float* E      = (const float*)d_in[2];
    const int*   words  = (const int*)d_in[3];
    const int*   tags   = (const int*)d_in[4];
    float*       out    = (float*)d_out;

    static int attr_done = 0;
    if (!attr_done) {
        cudaFuncSetAttribute(emit_kernel,
                             cudaFuncAttributeMaxDynamicSharedMemorySize, SMEM_EMIT);
        attr_done = 1;
    }
    emit_kernel<<<BB, 256, SMEM_EMIT>>>(ThetaB, E, words);
    forward_kernel<<<BB, 32>>>(WA, tags, out);
}

// round 17
// speedup vs baseline: 1.3036x; 1.3036x over previous
#include <cuda_runtime.h>
#include <cuda_bf16.h>
#include <math.h>
#include <stdint.h>

// Problem constants
#define KK    64
#define DD    512
#define TT    128
#define BB    512
#define BOS_T 63
#define EOS_T 62
#define LOG64 4.158883083359672f

#define BROW  1040            // B smem row stride bytes (512*2 + 16 pad)
#define SEQ_PER_CTA 4
#define NCTA  (BB / SEQ_PER_CTA)      // 128

// SMEM layout (bytes from dynamic base)
#define OFF_B    0                            // ThetaB bf16: 64 x BROW = 66560
#define OFF_SWB  66560                        // 4 x 126 x 64 f32 = 129024
#define SWB_SEQ  (126 * KK)                   // floats per seq
#define OFF_SAL  (OFF_SWB + 4 * SWB_SEQ * 4)  // 195584: 4 x 2 x 64 f32
#define OFF_RED  (OFF_SAL + 4 * 2 * KK * 4)   // 197632: 4 x 4 f32
#define SMEM_TOT (OFF_RED + 64)               // 197696

__device__ __forceinline__ uint32_t pk(float a, float b) {
    __nv_bfloat162 h = __floats2bfloat162_rn(a, b);
    return *reinterpret_cast<uint32_t*>(&h);
}
__device__ __forceinline__ uint32_t pk2(float2 v) { return pk(v.x, v.y); }

__device__ __forceinline__ void mma16816(float* c, uint32_t a0, uint32_t a1,
                                         uint32_t a2, uint32_t a3,
                                         uint32_t b0, uint32_t b1) {
    asm volatile(
        "mma.sync.aligned.m16n8k16.row.col.f32.bf16.bf16.f32 "
        "{%0,%1,%2,%3}, {%4,%5,%6,%7}, {%8,%9}, {%0,%1,%2,%3};"
        : "+f"(c[0]), "+f"(c[1]), "+f"(c[2]), "+f"(c[3])
        : "r"(a0), "r"(a1), "r"(a2), "r"(a3), "r"(b0), "r"(b1));
}

__device__ __forceinline__ void ldsm4(uint32_t& r0, uint32_t& r1,
                                      uint32_t& r2, uint32_t& r3, uint32_t addr) {
    asm volatile("ldmatrix.sync.aligned.m8n8.x4.shared.b16 {%0,%1,%2,%3}, [%4];"
                 : "=r"(r0), "=r"(r1), "=r"(r2), "=r"(r3) : "r"(addr));
}

// ---------------------------------------------------------------------------
// Fused kernel: one CTA handles 4 sequences; grid = 128 -> single wave.
// Phase 1: ThetaB -> bf16 SMEM (once).
// Phase 2: per seq, R14-proven barrier-free direct-LDG MMA mainloop;
//          epilogue exp(wb)/64 (cols 62/63 zeroed) -> SMEM swb (rows 1..126).
// Phase 3: four independent R11-proven forward recursions on 64-thread
//          groups (named barriers 1..4).
// ---------------------------------------------------------------------------
__global__ __launch_bounds__(256, 1)
void crf_fused_kernel(const float* __restrict__ WA,
                      const float* __restrict__ ThetaB,
                      const float* __restrict__ E,
                      const int*   __restrict__ words,
                      const int*   __restrict__ tags,
                      float*       __restrict__ out)
{
    extern __shared__ char sm[];
    float* swbS = (float*)(sm + OFF_SWB);
    float* salS = (float*)(sm + OFF_SAL);
    float* sred = (float*)(sm + OFF_RED);

    const int tid  = threadIdx.x;
    const int wid  = tid >> 5, lane = tid & 31;
    const int g    = lane >> 2, t4 = lane & 3;
    const int m0   = wid * 16;
    const int bb   = blockIdx.x;                 // sequences 4bb .. 4bb+3

    // ---- phase 1: stage ThetaB -> bf16 SMEM, full K (once) ----
    {
        const int row = tid >> 2, q = tid & 3;                 // 4 thr/row
        const float4* tp = (const float4*)(ThetaB + row * DD + q * 32);
        char* dst = sm + row * BROW + q * 64;
#pragma unroll
        for (int c = 0; c < 4; ++c) {
            float4 tr[8];
#pragma unroll
            for (int j = 0; j < 8; ++j) tr[j] = tp[c * 32 + j];
#pragma unroll
            for (int jj = 0; jj < 4; ++jj) {
                float4 g0 = tr[2 * jj], g1 = tr[2 * jj + 1];
                *(uint4*)(dst + c * 256 + jj * 16) =
                    make_uint4(pk(g0.x, g0.y), pk(g0.z, g0.w),
                               pk(g1.x, g1.y), pk(g1.z, g1.w));
            }
        }
    }
    __syncthreads();

    // B ldsm base (proven lane mapping, row stride BROW)
    const uint32_t base = (uint32_t)__cvta_generic_to_shared(sm);
    const uint32_t aB = base
        + (uint32_t)(((((lane >> 4) & 1) * 8 + (lane & 7)) * BROW)
        + ((lane >> 3) & 1) * 16);
    const int koff = 2 * t4;

    // ---- phase 2: emit 4 sequences (barrier-free mainloops) ----
    for (int s = 0; s < SEQ_PER_CTA; ++s) {
        const int b = 4 * bb + s;
        const float* p0 = E + (size_t)words[b * TT + m0 + g] * DD;
        const float* p1 = E + (size_t)words[b * TT + m0 + 8 + g] * DD;

        float acc[8][4];
#pragma unroll
        for (int nt = 0; nt < 8; ++nt)
#pragma unroll
            for (int r = 0; r < 4; ++r) acc[nt][r] = 0.f;

        float2 buf[2][8];
#define LOADG(grp, d)                                                    \
        {                                                                \
            const int s0 = (grp) * 2;                                    \
            (d)[0] = *(const float2*)(p0 + 16 * s0 + koff);              \
            (d)[1] = *(const float2*)(p0 + 16 * s0 + koff + 8);          \
            (d)[2] = *(const float2*)(p1 + 16 * s0 + koff);              \
            (d)[3] = *(const float2*)(p1 + 16 * s0 + koff + 8);          \
            (d)[4] = *(const float2*)(p0 + 16 * s0 + 16 + koff);         \
            (d)[5] = *(const float2*)(p0 + 16 * s0 + 16 + koff + 8);     \
            (d)[6] = *(const float2*)(p1 + 16 * s0 + 16 + koff);         \
            (d)[7] = *(const float2*)(p1 + 16 * s0 + 16 + koff + 8);     \
        }
        LOADG(0, buf[0]);
#pragma unroll
        for (int grp = 0; grp < 16; ++grp) {
            if (grp < 15) LOADG(grp + 1, buf[(grp + 1) & 1]);
            const float2* d = buf[grp & 1];
#pragma unroll
            for (int ss = 0; ss < 2; ++ss) {
                const int st = grp * 2 + ss;
                const uint32_t a0 = pk2(d[ss * 4 + 0]);   // row m0+g,   k lo
                const uint32_t a2 = pk2(d[ss * 4 + 1]);   // row m0+g,   k hi
                const uint32_t a1 = pk2(d[ss * 4 + 2]);   // row m0+8+g, k lo
                const uint32_t a3 = pk2(d[ss * 4 + 3]);   // row m0+8+g, k hi
#pragma unroll
                for (int i = 0; i < 4; ++i) {
                    uint32_t b0, b1, b2, b3;
                    ldsm4(b0, b1, b2, b3, aB + i * (16 * BROW) + st * 32);
                    mma16816(acc[2 * i],     a0, a1, a2, a3, b0, b1);
                    mma16816(acc[2 * i + 1], a0, a1, a2, a3, b2, b3);
                }
            }
        }
#undef LOADG

        // epilogue: exp/64, mask cols 62/63, write rows 1..126 to SMEM swb
        const float inv = 1.0f / 64.0f;
        float* sw = swbS + s * SWB_SEQ;
        const int t0 = m0 + g, t1 = m0 + 8 + g;
#pragma unroll
        for (int nt = 0; nt < 8; ++nt) {
            const int col = nt * 8 + t4 * 2;
            const bool msk = (col == EOS_T);
            float2 v0, v1;
            v0.x = msk ? 0.f : __expf(acc[nt][0]) * inv;
            v0.y = msk ? 0.f : __expf(acc[nt][1]) * inv;
            v1.x = msk ? 0.f : __expf(acc[nt][2]) * inv;
            v1.y = msk ? 0.f : __expf(acc[nt][3]) * inv;
            if (t0 >= 1 && t0 <= 126) *(float2*)(sw + (t0 - 1) * KK + col) = v0;
            if (t1 >= 1 && t1 <= 126) *(float2*)(sw + (t1 - 1) * KK + col) = v1;
        }
    }
    __syncthreads();

    // ---- phase 3: forward recursion, group s = tid>>6 handles seq 4bb+s ----
    const int s    = tid >> 6;
    const int k    = tid & 63;
    const int gw   = (tid >> 5) & 1;            // warp within group
    const int glane = tid & 31;
    const int b    = 4 * bb + s;
    const float* sw = swbS + s * SWB_SEQ;
    float* sal = salS + s * 2 * KK;
    float* red = sred + s * 4;

    // full A column for this k
    float A[KK];
#pragma unroll
    for (int j = 0; j < KK; ++j) A[j] = __expf(WA[j * KK + k]);

    // tagged closed form (t strided by 64 over 1..126)
    float tagc = 0.f;
    for (int t = k + 1; t <= 126; t += 64) {
        const int ct = tags[b * TT + t];
        const int pt = (t == 1) ? BOS_T : tags[b * TT + t - 1];
        tagc += __logf(sw[(t - 1) * KK + ct]) + LOG64 + WA[pt * KK + ct];
    }
    if (k == 63) tagc += WA[tags[b * TT + 126] * KK + EOS_T];
#pragma unroll
    for (int o = 16; o > 0; o >>= 1) tagc += __shfl_down_sync(0xffffffffu, tagc, o);
    if (glane == 0) red[gw] = tagc;

    // forward recursion (named barrier per group)
    float alph = A[BOS_T] * sw[k];              // t=1 row
    int bufi = 0;
    for (int t = 2; t <= 126; ++t) {
        sal[bufi * KK + k] = alph;
        asm volatile("bar.sync %0, 64;" :: "r"(s + 1) : "memory");
        const float4* av = (const float4*)(sal + bufi * KK);
        float s0 = 0.f, s1 = 0.f, s2 = 0.f, s3 = 0.f;
#pragma unroll
        for (int jj = 0; jj < 16; ++jj) {
            const float4 v = av[jj];
            s0 = fmaf(v.x, A[4 * jj + 0], s0);
            s1 = fmaf(v.y, A[4 * jj + 1], s1);
            s2 = fmaf(v.z, A[4 * jj + 2], s2);
            s3 = fmaf(v.w, A[4 * jj + 3], s3);
        }
        alph = ((s0 + s1) + (s2 + s3)) * sw[(t - 1) * KK + k];
        bufi ^= 1;
        // next iteration writes the other buffer; its bar fences reads.
    }

    float contrib = alph * __expf(WA[k * KK + EOS_T]);
#pragma unroll
    for (int o = 16; o > 0; o >>= 1) contrib += __shfl_down_sync(0xffffffffu, contrib, o);
    if (glane == 0) red[2 + gw] = contrib;
    asm volatile("bar.sync %0, 64;" :: "r"(s + 1) : "memory");

    if (k == 0)
        out[b] = (red[0] + red[1])
               - (__logf(red[2] + red[3]) + 126.0f * LOG64);
}

// ---------------------------------------------------------------------------
// Inputs: WA[64*64] f32, ThetaB[64*512] f32, E[100000*512] f32,
//         words[512*128] i32, tags[512*128] i32  ->  out f32[512]
// ---------------------------------------------------------------------------
extern "C" void kernel_launch(void* const* d_in, const int* in_sizes, int n_in,
                              void* d_out, int out_size)
{
    const float* WA     = (const float*)d_in[0];
    const float* ThetaB = (const float*)d_in[1];
    const float* E      = (const float*)d_in[2];
    const int*   words  = (const int*)d_in[3];
    const int*   tags   = (const int*)d_in[4];
    float*       out    = (float*)d_out;

    static int attr_done = 0;
    if (!attr_done) {
        cudaFuncSetAttribute(crf_fused_kernel,
                             cudaFuncAttributeMaxDynamicSharedMemorySize, SMEM_TOT);
        attr_done = 1;
    }
    crf_fused_kernel<<<NCTA, 256, SMEM_TOT>>>(WA, ThetaB, E, words, tags, out);
}